// round 3
// baseline (speedup 1.0000x reference)
#include <cuda_runtime.h>
#include <cuda_bf16.h>

// Problem constants (fixed by the dataset)
#define BB 16
#define TT 32641
#define EE 128
#define LL (TT + EE - 1)      // 32768 groups (power of two); == TT + 127
#define RT 64                  // rows per smem tile
#define WG 512                 // groups per block (chunk)
#define NCHUNK (LL / WG)       // 64
#define NTILE ((WG + EE - 1 + RT - 1) / RT)  // ceil(639/64) = 10

// Cross-replay state (zero at module load; reset by last block each run)
__device__ float g_acc;
__device__ unsigned int g_cnt;

// ---------------------------------------------------------------------------
// Single fused kernel.
// Block (chunk c, batch b) owns groups [t0, t0+WG), t0 = c*WG. It streams
// rows [t0-127, t0+WG) in RT-row tiles (double-buffered smem, reg-prefetch
// pipeline), walks anti-diagonals per tile accumulating S1/S2 into smem
// group accumulators, then computes var locally and contributes one float
// to the global accumulator. No global scratch arrays.
// smem: 2*RT*EE floats (64 KB tiles) + 2*WG floats (4 KB accumulators).
// ---------------------------------------------------------------------------
__global__ void __launch_bounds__(256) tcl_fused_kernel(const float* __restrict__ x,
                                                        float* __restrict__ out) {
    extern __shared__ float smem[];
    float* buf = smem;                    // 2 * RT*EE
    float* sA1 = smem + 2 * RT * EE;      // WG
    float* sA2 = sA1 + WG;                // WG

    const int c   = blockIdx.x;
    const int b   = blockIdx.y;
    const int tid = threadIdx.x;
    const int t0  = c * WG;
    const int rb  = t0 - (EE - 1);        // first row this chunk needs (may be <0)
    const float* xb = x + (size_t)b * TT * EE;

    // Zero group accumulators.
    #pragma unroll
    for (int i = tid; i < WG; i += 256) { sA1[i] = 0.0f; sA2[i] = 0.0f; }

    float4 reg[8];

    // Prefetch tile 0 (rows outside [0, TT) zero-filled).
    {
        const int r0 = rb;
        #pragma unroll
        for (int u = 0; u < 8; ++u) {
            int v    = tid + u * 256;
            int row  = v >> 5;            // / (EE/4)
            int colv = v & 31;            // % (EE/4)
            int gr   = r0 + row;
            reg[u] = (gr >= 0 && gr < TT)
                   ? __ldg((const float4*)(xb + (size_t)gr * EE) + colv)
                   : make_float4(0.f, 0.f, 0.f, 0.f);
        }
    }

    for (int kk = 0; kk < NTILE; ++kk) {
        float* cur = buf + (kk & 1) * (RT * EE);

        // Stage prefetched registers into the current smem buffer.
        #pragma unroll
        for (int u = 0; u < 8; ++u) {
            ((float4*)cur)[tid + u * 256] = reg[u];
        }
        __syncthreads();

        // Issue next tile's global loads immediately — keeps DRAM busy
        // while this tile is consumed from smem.
        if (kk + 1 < NTILE) {
            const int r0n = rb + (kk + 1) * RT;
            #pragma unroll
            for (int u = 0; u < 8; ++u) {
                int v    = tid + u * 256;
                int row  = v >> 5;
                int colv = v & 31;
                int gr   = r0n + row;
                reg[u] = (gr >= 0 && gr < TT)
                       ? __ldg((const float4*)(xb + (size_t)gr * EE) + colv)
                       : make_float4(0.f, 0.f, 0.f, 0.f);
            }
        }

        // Diagonal walk: thread d owns in-tile diagonal t = r0 + d.
        // Accumulate into smem group accumulators if t is in this chunk.
        // One thread per group per tile; cross-tile RMW ordered by syncs.
        const int r0 = rb + kk * RT;
        const int d  = tid;
        if (d < RT + EE - 1) {
            const int t   = r0 + d;
            const int idx = t - t0;
            if (idx >= 0 && idx < WG) {
                const int i_lo = max(0, d - (EE - 1));
                const int i_hi = min(RT - 1, d);
                float s1 = 0.0f, s2 = 0.0f;
                #pragma unroll 4
                for (int i = i_lo; i <= i_hi; ++i) {
                    float v = cur[i * EE + (d - i)];
                    s1 += v;
                    s2 = fmaf(v, v, s2);
                }
                sA1[idx] += s1;
                sA2[idx] += s2;
            }
        }
        // No trailing sync: next iteration's post-STS sync orders the
        // 2-apart double-buffer reuse and the accumulator RMWs.
    }
    __syncthreads();   // last tile's accumulator writes must be visible

    // Per-group variance with analytic counts; local then block reduce.
    float local = 0.0f;
    #pragma unroll
    for (int idx = tid; idx < WG; idx += 256) {
        int t  = t0 + idx;
        int ci = min(min(t + 1, EE), LL - t);
        float inv_c = 1.0f / (float)ci;
        float s1 = sA1[idx];
        float s2 = sA2[idx];
        float mean = s1 * inv_c;
        local += s2 * inv_c - mean * mean;
    }
    __shared__ float red[8];
    #pragma unroll
    for (int o = 16; o; o >>= 1) local += __shfl_down_sync(0xFFFFFFFFu, local, o);
    if ((tid & 31) == 0) red[tid >> 5] = local;
    __syncthreads();
    if (tid < 8) {
        float v = red[tid];
        #pragma unroll
        for (int o = 4; o; o >>= 1) v += __shfl_down_sync(0xFFu, v, o);
        if (tid == 0) {
            atomicAdd(&g_acc, v);
            __threadfence();
            unsigned int ticket = atomicAdd(&g_cnt, 1u);
            if (ticket == gridDim.x * gridDim.y - 1) {
                out[0] = g_acc * (0.1f / ((float)BB * (float)LL));
                g_acc = 0.0f;          // reset for next graph replay
                g_cnt = 0u;
                __threadfence();
            }
        }
    }
}

// ---------------------------------------------------------------------------
extern "C" void kernel_launch(void* const* d_in, const int* in_sizes, int n_in,
                              void* d_out, int out_size) {
    const float* x = (const float*)d_in[0];
    float* out = (float*)d_out;

    const int smem_bytes = (2 * RT * EE + 2 * WG) * (int)sizeof(float); // 68 KB
    cudaFuncSetAttribute(tcl_fused_kernel,
                         cudaFuncAttributeMaxDynamicSharedMemorySize, smem_bytes);

    dim3 grid(NCHUNK, BB);   // 64 x 16 = 1024 blocks
    tcl_fused_kernel<<<grid, 256, smem_bytes>>>(x, out);
}

// round 4
// speedup vs baseline: 1.5107x; 1.5107x over previous
#include <cuda_runtime.h>
#include <cuda_bf16.h>

// Problem constants (fixed by the dataset)
#define BB 16
#define TT 32641
#define EE 128
#define LL (TT + EE - 1)           // 32768 groups (power of two)
#define RR 64                      // rows per tile
#define TILES ((TT + RR - 1) / RR) // 511
#define TPC 4                      // tiles per chunk (per block)
#define CHUNKS 128                 // 128*4 = 512 >= 511

// Scratch: per-(batch, group) partial sums (4 MB total).
__device__ float g_S1[BB * LL];
__device__ float g_S2[BB * LL];

// ---------------------------------------------------------------------------
// Kernel 0: zero scratch (float4 stores) + output scalar.
// ---------------------------------------------------------------------------
__global__ void __launch_bounds__(256) tcl_init_kernel(float* __restrict__ out) {
    const int n4 = BB * LL / 4;      // 131072 float4 per array
    const int stride = gridDim.x * blockDim.x;
    float4 z = make_float4(0.f, 0.f, 0.f, 0.f);
    for (int i = blockIdx.x * blockDim.x + threadIdx.x; i < n4; i += stride) {
        ((float4*)g_S1)[i] = z;
        ((float4*)g_S2)[i] = z;
    }
    if (blockIdx.x == 0 && threadIdx.x == 0) out[0] = 0.0f;
}

// ---------------------------------------------------------------------------
// Kernel 1: software-pipelined anti-diagonal partial sums (R2's engine).
// Block (chunk, b): 4 tiles of 64 rows; regs->smem double buffer; LDGs for
// tile k+1 issued right after the sync so DRAM stays busy during compute.
// ---------------------------------------------------------------------------
__global__ void __launch_bounds__(256) tcl_diag_kernel(const float* __restrict__ x) {
    extern __shared__ float buf[];   // 2 * RR*EE floats = 64 KB

    const int b   = blockIdx.y;
    const int tid = threadIdx.x;
    const float* xb = x + (size_t)b * TT * EE;

    const int k0 = blockIdx.x * TPC;
    const int k1 = min(k0 + TPC, TILES);
    const int nk = k1 - k0;
    if (nk <= 0) return;

    float4 reg[8];

    // Prefetch tile k0 into registers (rows >= TT zero-filled).
    {
        const int r0 = k0 * RR;
        #pragma unroll
        for (int u = 0; u < 8; ++u) {
            int v    = tid + u * 256;
            int row  = v >> 5;       // / (EE/4)
            int colv = v & 31;       // % (EE/4)
            int gr   = r0 + row;
            reg[u] = (gr < TT)
                   ? __ldg((const float4*)(xb + (size_t)gr * EE) + colv)
                   : make_float4(0.f, 0.f, 0.f, 0.f);
        }
    }

    for (int kk = 0; kk < nk; ++kk) {
        float* cur = buf + (kk & 1) * (RR * EE);

        // Stage prefetched registers into the current smem buffer.
        #pragma unroll
        for (int u = 0; u < 8; ++u) {
            ((float4*)cur)[tid + u * 256] = reg[u];
        }
        __syncthreads();

        // Issue next tile's global loads immediately.
        if (kk + 1 < nk) {
            const int r0n = (k0 + kk + 1) * RR;
            #pragma unroll
            for (int u = 0; u < 8; ++u) {
                int v    = tid + u * 256;
                int row  = v >> 5;
                int colv = v & 31;
                int gr   = r0n + row;
                reg[u] = (gr < TT)
                       ? __ldg((const float4*)(xb + (size_t)gr * EE) + colv)
                       : make_float4(0.f, 0.f, 0.f, 0.f);
            }
        }

        // Diagonal walk: thread d owns group t = r0 + d within this tile.
        // cur[i*EE + (d-i)]: lanes d..d+31 at fixed i are consecutive ->
        // conflict-free.
        const int r0 = (k0 + kk) * RR;
        const int d  = tid;
        if (d < RR + EE - 1) {
            const int t    = r0 + d;
            const int tmax = min(r0 + RR, TT) - 1 + (EE - 1);
            if (t <= tmax) {
                const int i_lo = max(0, d - (EE - 1));
                const int i_hi = min(RR - 1, d);
                float s1 = 0.0f, s2 = 0.0f;
                #pragma unroll 4
                for (int i = i_lo; i <= i_hi; ++i) {
                    float v = cur[i * EE + (d - i)];
                    s1 += v;
                    s2 = fmaf(v, v, s2);
                }
                atomicAdd(&g_S1[b * LL + t], s1);
                atomicAdd(&g_S2[b * LL + t], s2);
            }
        }
        // Next iteration's post-STS sync orders the 2-apart buffer reuse.
    }
}

// ---------------------------------------------------------------------------
// Kernel 2: var = S2/c - (S1/c)^2 with analytic counts c[t]; mean; * 0.1.
// Read-only on scratch (no resets, no fences) — init re-zeroes each replay.
// ---------------------------------------------------------------------------
__global__ void __launch_bounds__(256) tcl_finalize_kernel(float* __restrict__ out) {
    __shared__ float red[8];
    float local = 0.0f;
    const int stride = gridDim.x * blockDim.x;
    for (int g = blockIdx.x * blockDim.x + threadIdx.x; g < BB * LL; g += stride) {
        int t  = g & (LL - 1);                       // LL is a power of two
        int ci = min(min(t + 1, EE), LL - t);
        float inv_c = 1.0f / (float)ci;
        float s1 = g_S1[g];
        float s2 = g_S2[g];
        float mean = s1 * inv_c;
        local += s2 * inv_c - mean * mean;
    }
    #pragma unroll
    for (int o = 16; o; o >>= 1) local += __shfl_down_sync(0xFFFFFFFFu, local, o);
    if ((threadIdx.x & 31) == 0) red[threadIdx.x >> 5] = local;
    __syncthreads();
    if (threadIdx.x < 8) {
        float v = red[threadIdx.x];
        #pragma unroll
        for (int o = 4; o; o >>= 1) v += __shfl_down_sync(0xFFu, v, o);
        if (threadIdx.x == 0) {
            atomicAdd(out, v * (0.1f / ((float)BB * (float)LL)));
        }
    }
}

// ---------------------------------------------------------------------------
extern "C" void kernel_launch(void* const* d_in, const int* in_sizes, int n_in,
                              void* d_out, int out_size) {
    const float* x = (const float*)d_in[0];
    float* out = (float*)d_out;

    tcl_init_kernel<<<512, 256>>>(out);

    const int diag_smem = 2 * RR * EE * (int)sizeof(float);  // 64 KB
    cudaFuncSetAttribute(tcl_diag_kernel,
                         cudaFuncAttributeMaxDynamicSharedMemorySize, diag_smem);
    dim3 grid(CHUNKS, BB);
    tcl_diag_kernel<<<grid, 256, diag_smem>>>(x);

    tcl_finalize_kernel<<<256, 256>>>(out);
}

// round 5
// speedup vs baseline: 1.9430x; 1.2861x over previous
#include <cuda_runtime.h>
#include <cuda_bf16.h>

// Problem constants (fixed by the dataset)
#define BB 16
#define TT 32641
#define EE 128
#define LL (TT + EE - 1)            // 32768 groups (power of two)
#define RR 32                       // rows per tile (small -> high occupancy)
#define TILES ((TT + RR - 1) / RR)  // 1021
#define TPC 8                       // tiles per chunk (per block)
#define CHUNKS ((TILES + TPC - 1) / TPC) // 128

// Scratch: per-(batch, group) partial sums (4 MB total).
__device__ float g_S1[BB * LL];
__device__ float g_S2[BB * LL];

// ---------------------------------------------------------------------------
// Kernel 0: zero scratch (float4 stores) + output scalar.
// 131072 threads, exactly one float4 per array each.
// ---------------------------------------------------------------------------
__global__ void __launch_bounds__(256) tcl_init_kernel(float* __restrict__ out) {
    const int i = blockIdx.x * blockDim.x + threadIdx.x;   // < BB*LL/4
    float4 z = make_float4(0.f, 0.f, 0.f, 0.f);
    ((float4*)g_S1)[i] = z;
    ((float4*)g_S2)[i] = z;
    if (i == 0) out[0] = 0.0f;
}

// ---------------------------------------------------------------------------
// Kernel 1: software-pipelined anti-diagonal partial sums.
// RR=32 rows/tile -> 2*16KB smem double buffer -> 6 CTAs/SM.
// Per tile: staged regs -> smem, sync, issue next tile's LDGs, walk diagonals.
// ---------------------------------------------------------------------------
__global__ void __launch_bounds__(256) tcl_diag_kernel(const float* __restrict__ x) {
    extern __shared__ float buf[];   // 2 * RR*EE floats = 32 KB

    const int b   = blockIdx.y;
    const int tid = threadIdx.x;
    const float* xb = x + (size_t)b * TT * EE;

    const int k0 = blockIdx.x * TPC;
    const int k1 = min(k0 + TPC, TILES);
    const int nk = k1 - k0;
    if (nk <= 0) return;

    float4 reg[4];

    // Prefetch tile k0 into registers (rows >= TT zero-filled).
    {
        const int r0 = k0 * RR;
        #pragma unroll
        for (int u = 0; u < 4; ++u) {
            int v    = tid + u * 256;
            int row  = v >> 5;       // / (EE/4)
            int colv = v & 31;       // % (EE/4)
            int gr   = r0 + row;
            reg[u] = (gr < TT)
                   ? __ldg((const float4*)(xb + (size_t)gr * EE) + colv)
                   : make_float4(0.f, 0.f, 0.f, 0.f);
        }
    }

    for (int kk = 0; kk < nk; ++kk) {
        float* cur = buf + (kk & 1) * (RR * EE);

        // Stage prefetched registers into the current smem buffer.
        #pragma unroll
        for (int u = 0; u < 4; ++u) {
            ((float4*)cur)[tid + u * 256] = reg[u];
        }
        __syncthreads();

        // Issue next tile's global loads immediately — DRAM busy during compute.
        if (kk + 1 < nk) {
            const int r0n = (k0 + kk + 1) * RR;
            #pragma unroll
            for (int u = 0; u < 4; ++u) {
                int v    = tid + u * 256;
                int row  = v >> 5;
                int colv = v & 31;
                int gr   = r0n + row;
                reg[u] = (gr < TT)
                       ? __ldg((const float4*)(xb + (size_t)gr * EE) + colv)
                       : make_float4(0.f, 0.f, 0.f, 0.f);
            }
        }

        // Diagonal walk: thread d owns group t = r0 + d within this tile.
        // cur[i*EE + (d-i)]: lanes d..d+31 at fixed i hit consecutive
        // addresses -> conflict-free.
        const int r0 = (k0 + kk) * RR;
        const int d  = tid;
        if (d < RR + EE - 1) {                     // 159 diagonals
            const int t    = r0 + d;
            const int tmax = min(r0 + RR, TT) - 1 + (EE - 1);
            if (t <= tmax) {
                const int i_lo = max(0, d - (EE - 1));
                const int i_hi = min(RR - 1, d);
                float s1 = 0.0f, s2 = 0.0f;
                #pragma unroll 4
                for (int i = i_lo; i <= i_hi; ++i) {
                    float v = cur[i * EE + (d - i)];
                    s1 += v;
                    s2 = fmaf(v, v, s2);
                }
                atomicAdd(&g_S1[b * LL + t], s1);
                atomicAdd(&g_S2[b * LL + t], s2);
            }
        }
        // Next iteration's post-STS sync orders the 2-apart buffer reuse.
    }
}

// ---------------------------------------------------------------------------
// Kernel 2: var = S2/c - (S1/c)^2, mean over (b,t), * 0.1.
// 131072 threads, each loads exactly ONE float4 from each array (max MLP,
// no serial loop) -> fully parallel latency, ~2-3us.
// ---------------------------------------------------------------------------
__global__ void __launch_bounds__(256) tcl_finalize_kernel(float* __restrict__ out) {
    __shared__ float red[8];
    const int i = blockIdx.x * blockDim.x + threadIdx.x;   // < BB*LL/4
    float4 s1v = ((const float4*)g_S1)[i];
    float4 s2v = ((const float4*)g_S2)[i];

    float local = 0.0f;
    const int g0 = i * 4;
    #pragma unroll
    for (int j = 0; j < 4; ++j) {
        int t  = (g0 + j) & (LL - 1);              // LL is a power of two
        int ci = min(min(t + 1, EE), LL - t);
        float inv_c = 1.0f / (float)ci;
        float s1 = (j == 0) ? s1v.x : (j == 1) ? s1v.y : (j == 2) ? s1v.z : s1v.w;
        float s2 = (j == 0) ? s2v.x : (j == 1) ? s2v.y : (j == 2) ? s2v.z : s2v.w;
        float mean = s1 * inv_c;
        local += s2 * inv_c - mean * mean;
    }

    #pragma unroll
    for (int o = 16; o; o >>= 1) local += __shfl_down_sync(0xFFFFFFFFu, local, o);
    if ((threadIdx.x & 31) == 0) red[threadIdx.x >> 5] = local;
    __syncthreads();
    if (threadIdx.x < 8) {
        float v = red[threadIdx.x];
        #pragma unroll
        for (int o = 4; o; o >>= 1) v += __shfl_down_sync(0xFFu, v, o);
        if (threadIdx.x == 0) {
            atomicAdd(out, v * (0.1f / ((float)BB * (float)LL)));
        }
    }
}

// ---------------------------------------------------------------------------
extern "C" void kernel_launch(void* const* d_in, const int* in_sizes, int n_in,
                              void* d_out, int out_size) {
    const float* x = (const float*)d_in[0];
    float* out = (float*)d_out;

    tcl_init_kernel<<<BB * LL / 4 / 256, 256>>>(out);      // 512 blocks

    const int diag_smem = 2 * RR * EE * (int)sizeof(float);  // 32 KB
    cudaFuncSetAttribute(tcl_diag_kernel,
                         cudaFuncAttributeMaxDynamicSharedMemorySize, diag_smem);
    dim3 grid(CHUNKS, BB);                                 // 128 x 16
    tcl_diag_kernel<<<grid, 256, diag_smem>>>(x);

    tcl_finalize_kernel<<<BB * LL / 4 / 256, 256>>>(out);  // 512 blocks
}